// round 14
// baseline (speedup 1.0000x reference)
#include <cuda_runtime.h>
#include <cuda_fp16.h>
#include <stdint.h>

#define DM    1024
#define NH    16
#define DK    64
#define BATCH 32
#define SEQ   512
#define MTOK  (BATCH*SEQ)   // 16384
#define EPSV  1e-6f

#define BM 256
#define BN 128
#define BK 64                        // halves per K chunk (128B row)
#define NCH (DM/BK)                  // 16
#define ROWB 144                     // padded row stride in bytes (128 + 16)
#define STAGE_BYTES ((BM+BN)*ROWB)   // 55296
#define SMEM_BYTES (3*STAGE_BYTES)   // 165888

// -------- scratch (static __device__, no runtime allocation) --------
__device__ __half g_xh[(size_t)MTOK * DM];       // half(x)
__device__ __half g_wth[4][(size_t)DM * DM];     // transposed half W{q,k,v,o}: [N,K]
__device__ __half g_qfh[(size_t)MTOK * DM];      // phi(Q) half, head-major [B,H,N,Dk]
__device__ __half g_kfh[(size_t)MTOK * DM];      // phi(K) half, head-major
__device__ __half g_vh [(size_t)MTOK * DM];      // V half, head-major
__device__ __half g_ath[(size_t)MTOK * DM];      // attn out half, token-major [B,N,H,Dk]
__device__ __half g_kvT[(size_t)BATCH * NH * DK * DK];  // kv^T [e][d], half
__device__ float  g_ks[(size_t)BATCH * NH * DK];

// ------------------------ helpers ------------------------
__device__ __forceinline__ uint32_t s2u(const void* p) {
    return (uint32_t)__cvta_generic_to_shared(p);
}
__device__ __forceinline__ void mma_f16(float* c, const uint32_t* a, const uint32_t* b) {
    asm volatile(
        "mma.sync.aligned.m16n8k16.row.col.f32.f16.f16.f32 "
        "{%0,%1,%2,%3},{%4,%5,%6,%7},{%8,%9},{%0,%1,%2,%3};"
        : "+f"(c[0]), "+f"(c[1]), "+f"(c[2]), "+f"(c[3])
        : "r"(a[0]), "r"(a[1]), "r"(a[2]), "r"(a[3]),
          "r"(b[0]), "r"(b[1]));
}
__device__ __forceinline__ void ldsm_x4(uint32_t& r0, uint32_t& r1, uint32_t& r2,
                                        uint32_t& r3, uint32_t addr) {
    asm volatile("ldmatrix.sync.aligned.m8n8.x4.shared.b16 {%0,%1,%2,%3}, [%4];"
                 : "=r"(r0), "=r"(r1), "=r"(r2), "=r"(r3) : "r"(addr));
}
__device__ __forceinline__ void ldsm_x4t(uint32_t& r0, uint32_t& r1, uint32_t& r2,
                                         uint32_t& r3, uint32_t addr) {
    asm volatile("ldmatrix.sync.aligned.m8n8.x4.trans.shared.b16 {%0,%1,%2,%3}, [%4];"
                 : "=r"(r0), "=r"(r1), "=r"(r2), "=r"(r3) : "r"(addr));
}

// ------------------------ fused fp16 GEMM body ------------------------
// A:[M,1024] half row-major; Bt:[N,1024] half row-major (W^T)
// BM=256 x BN=128 CTA tile; 16 warps in 4x4, each 64x32 (R10-proven micro-tile).
// mode 0: bias+phi -> half head-major; 1: bias -> half head-major; 2: bias -> fp32 row-major
__device__ __forceinline__ void gemm_body(
    const __half* __restrict__ A, const __half* __restrict__ Bt,
    const float* __restrict__ bias, float* __restrict__ dstf,
    __half* __restrict__ dsth, int m0, int n0, int mode)
{
    extern __shared__ char smc[];
    const uint32_t smb = s2u(smc);
    const int tid  = threadIdx.x;
    const int wid  = tid >> 5, lane = tid & 31;
    const int wm   = wid >> 2, wn   = wid & 3;   // 4 x 4 warp grid
    const int g    = lane >> 2, tig = lane & 3;

    float acc[4][4][4];
    #pragma unroll
    for (int mt = 0; mt < 4; mt++)
        #pragma unroll
        for (int nt = 0; nt < 4; nt++)
            #pragma unroll
            for (int q = 0; q < 4; q++) acc[mt][nt][q] = 0.f;

    const uint32_t aOff = (uint32_t)((lane & 15) * ROWB + (lane >> 4) * 16);
    const uint32_t bOff = (uint32_t)(((lane & 7) + ((lane >> 4) << 3)) * ROWB
                                     + ((lane >> 3) & 1) * 16);

    // load one K-chunk: A rows 0..255, B rows 256..383
    auto issue_load = [&](int s, int k0) {
        const uint32_t sb = smb + (uint32_t)s * STAGE_BYTES;
        #pragma unroll
        for (int i = 0; i < 4; i++) {                 // A: 2048 segs / 512 thr
            int idx = tid + i * 512, row = idx >> 3, seg = idx & 7;
            const __half* src = A + (size_t)(m0 + row) * DM + k0 + seg * 8;
            asm volatile("cp.async.cg.shared.global [%0], [%1], 16;"
                         :: "r"(sb + (uint32_t)(row * ROWB + seg * 16)), "l"(src));
        }
        #pragma unroll
        for (int i = 0; i < 2; i++) {                 // B: 1024 segs
            int idx = tid + i * 512, row = idx >> 3, seg = idx & 7;
            const __half* src = Bt + (size_t)(n0 + row) * DM + k0 + seg * 8;
            asm volatile("cp.async.cg.shared.global [%0], [%1], 16;"
                         :: "r"(sb + (uint32_t)((256 + row) * ROWB + seg * 16)), "l"(src));
        }
        asm volatile("cp.async.commit_group;");
    };

    issue_load(0, 0);
    issue_load(1, BK);

    #pragma unroll 1
    for (int kc = 0; kc < NCH; kc++) {
        if (kc < NCH - 1) asm volatile("cp.async.wait_group 1;");
        else              asm volatile("cp.async.wait_group 0;");
        __syncthreads();

        if (kc + 2 < NCH) issue_load((kc + 2) % 3, (kc + 2) * BK);

        const uint32_t sb    = smb + (uint32_t)(kc % 3) * STAGE_BYTES;
        const uint32_t aWarp = sb + (uint32_t)(wm * 64) * ROWB + aOff;
        const uint32_t bWarp = sb + (uint32_t)(256 + wn * 32) * ROWB + bOff;

        #pragma unroll
        for (int kk = 0; kk < 4; kk++) {
            uint32_t a[4][4], b[4][2];
            #pragma unroll
            for (int mt = 0; mt < 4; mt++)
                ldsm_x4(a[mt][0], a[mt][1], a[mt][2], a[mt][3],
                        aWarp + (uint32_t)(mt * 16 * ROWB + kk * 32));
            ldsm_x4(b[0][0], b[0][1], b[1][0], b[1][1], bWarp + (uint32_t)(kk * 32));
            ldsm_x4(b[2][0], b[2][1], b[3][0], b[3][1],
                    bWarp + (uint32_t)(16 * ROWB + kk * 32));
            #pragma unroll
            for (int mt = 0; mt < 4; mt++)
                #pragma unroll
                for (int nt = 0; nt < 4; nt++)
                    mma_f16(acc[mt][nt], a[mt], b[nt]);
        }
    }

    const int mbase = m0 + wm * 64;
    const int nb    = n0 + wn * 32;
    #pragma unroll
    for (int mt = 0; mt < 4; mt++) {
        #pragma unroll
        for (int half = 0; half < 2; half++) {
            const int m = mbase + mt * 16 + g + half * 8;
            #pragma unroll
            for (int nt = 0; nt < 4; nt++) {
                const int c = nb + nt * 8 + 2 * tig;
                float v0 = acc[mt][nt][half * 2 + 0] + bias[c];
                float v1 = acc[mt][nt][half * 2 + 1] + bias[c + 1];
                if (mode == 0) {
                    v0 = (v0 > 0.f) ? (v0 + 1.f) : __expf(v0);
                    v1 = (v1 > 0.f) ? (v1 + 1.f) : __expf(v1);
                }
                if (mode == 2) {
                    *(float2*)&dstf[(size_t)m * DM + c] = make_float2(v0, v1);
                } else {
                    const int b2 = m >> 9, n = m & 511;
                    const int h = c >> 6, d = c & 63;
                    *(__half2*)&dsth[((((size_t)(b2 * NH + h)) * SEQ + n) << 6) + d] =
                        __floats2half2_rn(v0, v1);
                }
            }
        }
    }
}

// ------------------------ kernels ------------------------
__global__ __launch_bounds__(512, 1) void qkv_mma(
    const float* __restrict__ bq, const float* __restrict__ bk, const float* __restrict__ bv)
{
    const int z = blockIdx.z;
    const float* bias = (z == 0) ? bq : (z == 1) ? bk : bv;
    __half* dst       = (z == 0) ? g_qfh : (z == 1) ? g_kfh : g_vh;
    gemm_body(g_xh, g_wth[z], bias, nullptr, dst,
              blockIdx.y * BM, blockIdx.x * BN, (z < 2) ? 0 : 1);
}

__global__ __launch_bounds__(512, 1) void out_mma(
    const float* __restrict__ bo, float* __restrict__ out)
{
    gemm_body(g_ath, g_wth[3], bo, out, nullptr, blockIdx.y * BM, blockIdx.x * BN, 2);
}

__global__ __launch_bounds__(256) void cvt_x_kernel(const float* __restrict__ x)
{
    int idx = blockIdx.x * 256 + threadIdx.x;
    float4 v = ((const float4*)x)[idx];
    ((__half2*)g_xh)[idx * 2 + 0] = __floats2half2_rn(v.x, v.y);
    ((__half2*)g_xh)[idx * 2 + 1] = __floats2half2_rn(v.z, v.w);
}

__global__ __launch_bounds__(256) void transpose_w(
    const float* __restrict__ Wq, const float* __restrict__ Wk,
    const float* __restrict__ Wv, const float* __restrict__ Wo)
{
    const int z = blockIdx.z;
    const float* W = (z == 0) ? Wq : (z == 1) ? Wk : (z == 2) ? Wv : Wo;
    __half* dst = g_wth[z];
    __shared__ float t[32][33];
    const int k0 = blockIdx.x * 32, n0 = blockIdx.y * 32;
    const int tx = threadIdx.x & 31, ty = threadIdx.x >> 5;
    #pragma unroll
    for (int i = 0; i < 4; i++)
        t[ty + i*8][tx] = W[(size_t)(k0 + ty + i*8) * DM + n0 + tx];
    __syncthreads();
    #pragma unroll
    for (int i = 0; i < 4; i++)
        dst[(size_t)(n0 + ty + i*8) * DM + k0 + tx] = __float2half_rn(t[tx][ty + i*8]);
}

// K2: kv^T[e][d] = sum_n kf[n][d]*v[n][e] via HMMA (trans ldmatrix); fused ksum. (R10)
#define KVROW 72   // padded row stride in halves (144B)
__global__ __launch_bounds__(128) void kv_kernel()
{
    const int bh = blockIdx.x;
    const __half* kf = g_kfh + (size_t)bh * SEQ * DK;
    const __half* v  = g_vh  + (size_t)bh * SEQ * DK;

    __shared__ __half kfs[2][64 * KVROW];
    __shared__ __half vs [2][64 * KVROW];

    const int tid  = threadIdx.x;
    const int wid  = tid >> 5, lane = tid & 31;
    const int wm   = wid >> 1, wn = wid & 1;       // 2x2 warp grid
    const int d_base = wm * 32, e_base = wn * 32;
    const int g8   = lane >> 3, r8 = lane & 7;
    const int g    = lane >> 2, tig = lane & 3;

    const uint32_t aTO = (uint32_t)((((g8 >> 1) * 8) + r8) * 2 * KVROW + ((g8 & 1) * 8) * 2);
    const uint32_t bTO = (uint32_t)((((g8 & 1) * 8) + r8) * 2 * KVROW + ((g8 >> 1) * 8) * 2);

    auto issue = [&](int s, int c) {
        uint32_t dk = s2u(&kfs[s][0]);
        uint32_t dv = s2u(&vs [s][0]);
        #pragma unroll
        for (int i = 0; i < 4; i++) {
            int idx = tid + i * 128, row = idx >> 3, seg = idx & 7;
            uint32_t off = (uint32_t)(row * (KVROW * 2) + seg * 16);
            const __half* sk = kf + (size_t)(c + row) * 64 + seg * 8;
            const __half* sv = v  + (size_t)(c + row) * 64 + seg * 8;
            asm volatile("cp.async.cg.shared.global [%0], [%1], 16;" :: "r"(dk + off), "l"(sk));
            asm volatile("cp.async.cg.shared.global [%0], [%1], 16;" :: "r"(dv + off), "l"(sv));
        }
        asm volatile("cp.async.commit_group;");
    };

    float acc[2][4][4];
    #pragma unroll
    for (int mt = 0; mt < 2; mt++)
        #pragma unroll
        for (int nt = 0; nt < 4; nt++)
            #pragma unroll
            for (int q = 0; q < 4; q++) acc[mt][nt][q] = 0.f;
    float ks = 0.f;

    issue(0, 0);
    for (int cc = 0; cc < SEQ / 64; cc++) {
        const int buf = cc & 1;
        if (cc + 1 < SEQ / 64) {
            issue(buf ^ 1, (cc + 1) * 64);
            asm volatile("cp.async.wait_group 1;");
        } else {
            asm volatile("cp.async.wait_group 0;");
        }
        __syncthreads();

        const uint32_t kb = s2u(&kfs[buf][0]);
        const uint32_t vb = s2u(&vs [buf][0]);

        #pragma unroll
        for (int kk = 0; kk < 4; kk++) {
            const uint32_t nb0 = (uint32_t)(kk * 16) * (KVROW * 2);
            uint32_t a[2][4], b[4][2];
            #pragma unroll
            for (int mt = 0; mt < 2; mt++)
                ldsm_x4t(a[mt][0], a[mt][1], a[mt][2], a[mt][3],
                         kb + nb0 + (uint32_t)(d_base + mt * 16) * 2 + aTO);
            #pragma unroll
            for (int p = 0; p < 2; p++) {
                uint32_t addr = vb + nb0 + (uint32_t)(e_base + p * 16) * 2 + bTO;
                ldsm_x4t(b[p*2][0], b[p*2][1], b[p*2+1][0], b[p*2+1][1], addr);
            }
            #pragma unroll
            for (int mt = 0; mt < 2; mt++)
                #pragma unroll
                for (int nt = 0; nt < 4; nt++)
                    mma_f16(acc[mt][nt], a[mt], b[nt]);
        }

        if (tid < 64) {
            #pragma unroll 8
            for (int n = 0; n < 64; n++)
                ks += __half2float(kfs[buf][n * KVROW + tid]);
        }
        __syncthreads();
    }

    __half* kvt = g_kvT + (size_t)bh * DK * DK;
    #pragma unroll
    for (int mt = 0; mt < 2; mt++) {
        #pragma unroll
        for (int half = 0; half < 2; half++) {
            const int d = d_base + mt * 16 + g + half * 8;
            #pragma unroll
            for (int nt = 0; nt < 4; nt++) {
                const int e = e_base + nt * 8 + 2 * tig;
                kvt[(size_t)e * DK + d]       = __float2half_rn(acc[mt][nt][half*2+0]);
                kvt[(size_t)(e+1) * DK + d]   = __float2half_rn(acc[mt][nt][half*2+1]);
            }
        }
    }
    if (tid < 64) g_ks[(size_t)bh * DK + tid] = ks;
}

// K3: out = qf @ kv / den via HMMA. 256 threads (8 warps), grid 512. (R10)
#define AT_QBYTES (SEQ * KVROW * 2)        // 73728
#define AT_KVOFF  AT_QBYTES
#define AT_KSOFF  (AT_KVOFF + 64 * KVROW * 2)   // 82944
#define AT_DENOFF (AT_KSOFF + 64 * 4)           // 83200
#define AT_SMEM   (AT_DENOFF + SEQ * 4)         // 85248
__global__ __launch_bounds__(256) void attn_kernel()
{
    const int bh = blockIdx.x;
    const int b = bh >> 4, h = bh & 15;

    extern __shared__ char smc[];
    __half* qfs = (__half*)smc;
    float*  kss = (float*)(smc + AT_KSOFF);
    float*  den = (float*)(smc + AT_DENOFF);
    const uint32_t smb = s2u(smc);

    const int tid  = threadIdx.x;
    const int wid  = tid >> 5, lane = tid & 31;
    const int g    = lane >> 2, tig = lane & 3;

    const __half* qf  = g_qfh + (size_t)bh * SEQ * DK;
    const __half* kvt = g_kvT + (size_t)bh * DK * DK;

    {
        uint32_t dq = smb;
        #pragma unroll
        for (int i = 0; i < 16; i++) {
            int idx = tid + i * 256, row = idx >> 3, seg = idx & 7;
            const __half* src = qf + (size_t)row * 64 + seg * 8;
            asm volatile("cp.async.cg.shared.global [%0], [%1], 16;"
                         :: "r"(dq + (uint32_t)(row * (KVROW*2) + seg * 16)), "l"(src));
        }
        uint32_t dk = smb + AT_KVOFF;
        #pragma unroll
        for (int i = 0; i < 2; i++) {
            int idx = tid + i * 256, row = idx >> 3, seg = idx & 7;
            const __half* src = kvt + (size_t)row * 64 + seg * 8;
            asm volatile("cp.async.cg.shared.global [%0], [%1], 16;"
                         :: "r"(dk + (uint32_t)(row * (KVROW*2) + seg * 16)), "l"(src));
        }
        asm volatile("cp.async.commit_group;");
    }
    if (tid < 64) kss[tid] = g_ks[(size_t)bh * DK + tid];
    asm volatile("cp.async.wait_group 0;");
    __syncthreads();

    #pragma unroll
    for (int rr = 0; rr < 2; rr++) {
        const int n = tid + rr * 256;
        const __half* qr = qfs + (size_t)n * KVROW;
        float dsum = 0.f;
        #pragma unroll 16
        for (int d = 0; d < 64; d++) dsum += __half2float(qr[d]) * kss[d];
        den[n] = 1.f / (dsum + EPSV);
    }
    __syncthreads();

    const uint32_t aOff = (uint32_t)((lane & 15) * (KVROW*2) + (lane >> 4) * 16);
    const uint32_t bOff = (uint32_t)(((lane & 7) + ((lane >> 4) << 3)) * (KVROW*2)
                                     + ((lane >> 3) & 1) * 16);
    const int m_base = wid * 64;
    const uint32_t aWarp = smb + (uint32_t)m_base * (KVROW*2) + aOff;
    const uint32_t bWarp = smb + AT_KVOFF + bOff;

    __half* outp = g_ath;
    #pragma unroll
    for (int nh = 0; nh < 2; nh++) {
        float acc[4][4][4];
        #pragma unroll
        for (int mt = 0; mt < 4; mt++)
            #pragma unroll
            for (int nt = 0; nt < 4; nt++)
                #pragma unroll
                for (int q = 0; q < 4; q++) acc[mt][nt][q] = 0.f;

        #pragma unroll
        for (int kk = 0; kk < 4; kk++) {
            uint32_t a[4][4], b[4][2];
            #pragma unroll
            for (int mt = 0; mt < 4; mt++)
                ldsm_x4(a[mt][0], a[mt][1], a[mt][2], a[mt][3],
                        aWarp + (uint32_t)(mt * 16 * (KVROW*2) + kk * 32));
            ldsm_x4(b[0][0], b[0][1], b[1][0], b[1][1],
                    bWarp + (uint32_t)((nh * 32) * (KVROW*2) + kk * 32));
            ldsm_x4(b[2][0], b[2][1], b[3][0], b[3][1],
                    bWarp + (uint32_t)((nh * 32 + 16) * (KVROW*2) + kk * 32));
            #pragma unroll
            for (int mt = 0; mt < 4; mt++)
                #pragma unroll
                for (int nt = 0; nt < 4; nt++)
                    mma_f16(acc[mt][nt], a[mt], b[nt]);
        }

        #pragma unroll
        for (int mt = 0; mt < 4; mt++) {
            #pragma unroll
            for (int half = 0; half < 2; half++) {
                const int m = m_base + mt * 16 + g + half * 8;
                const float inv = den[m];
                const size_t o = (((size_t)(b * SEQ + m)) * NH + h) * 64;
                #pragma unroll
                for (int nt = 0; nt < 4; nt++) {
                    const int e = nh * 32 + nt * 8 + 2 * tig;
                    *(__half2*)&outp[o + e] = __floats2half2_rn(
                        acc[mt][nt][half*2+0] * inv, acc[mt][nt][half*2+1] * inv);
                }
            }
        }
    }
}

// ---------------------------------------------------------------
extern "C" void kernel_launch(void* const* d_in, const int* in_sizes, int n_in,
                              void* d_out, int out_size)
{
    const float* x  = (const float*)d_in[0];
    const float* Wq = (const float*)d_in[1];
    const float* bq = (const float*)d_in[2];
    const float* Wk = (const float*)d_in[3];
    const float* bk = (const float*)d_in[4];
    const float* Wv = (const float*)d_in[5];
    const float* bv = (const float*)d_in[6];
    const float* Wo = (const float*)d_in[7];
    const float* bo = (const float*)d_in[8];
    float* out = (float*)d_out;

    cudaFuncSetAttribute(qkv_mma, cudaFuncAttributeMaxDynamicSharedMemorySize, SMEM_BYTES);
    cudaFuncSetAttribute(out_mma, cudaFuncAttributeMaxDynamicSharedMemorySize, SMEM_BYTES);
    cudaFuncSetAttribute(attn_kernel, cudaFuncAttributeMaxDynamicSharedMemorySize, AT_SMEM);

    cvt_x_kernel<<<(MTOK * DM / 4) / 256, 256>>>(x);
    transpose_w<<<dim3(DM/32, DM/32, 4), 256>>>(Wq, Wk, Wv, Wo);

    dim3 gq(DM / BN, MTOK / BM, 3);          // (8, 64, 3)
    qkv_mma<<<gq, 512, SMEM_BYTES>>>(bq, bk, bv);

    kv_kernel<<<BATCH * NH, 128>>>();
    attn_kernel<<<BATCH * NH, 256, AT_SMEM>>>();

    dim3 go(DM / BN, MTOK / BM);             // (8, 64)
    out_mma<<<go, 512, SMEM_BYTES>>>(bo, out);
}

// round 15
// speedup vs baseline: 1.0911x; 1.0911x over previous
#include <cuda_runtime.h>
#include <cuda_fp16.h>
#include <stdint.h>

#define DM    1024
#define NH    16
#define DK    64
#define BATCH 32
#define SEQ   512
#define MTOK  (BATCH*SEQ)   // 16384
#define EPSV  1e-6f

#define BM 128
#define BN 128
#define BK 64                        // halves per K chunk (128B row)
#define NCH (DM/BK)                  // 16
#define ROWB 144                     // padded row stride in bytes (128 + 16)
#define STAGE_BYTES ((BM+BN)*ROWB)   // 36864
#define SMEM_BYTES (2*STAGE_BYTES)   // 73728  (2 stages -> 2 CTAs/SM)

// -------- scratch (static __device__, no runtime allocation) --------
__device__ __half g_xh[(size_t)MTOK * DM];       // half(x)
__device__ __half g_wth[4][(size_t)DM * DM];     // transposed half W{q,k,v,o}: [N,K]
__device__ __half g_qfh[(size_t)MTOK * DM];      // phi(Q) half, head-major [B,H,N,Dk]
__device__ __half g_kfh[(size_t)MTOK * DM];      // phi(K) half, head-major
__device__ __half g_vh [(size_t)MTOK * DM];      // V half, head-major
__device__ __half g_ath[(size_t)MTOK * DM];      // attn out half, token-major [B,N,H,Dk]
__device__ __half g_kvT[(size_t)BATCH * NH * DK * DK];  // kv^T [e][d], half
__device__ float  g_ks[(size_t)BATCH * NH * DK];

// ------------------------ helpers ------------------------
__device__ __forceinline__ uint32_t s2u(const void* p) {
    return (uint32_t)__cvta_generic_to_shared(p);
}
__device__ __forceinline__ void mma_f16(float* c, const uint32_t* a, const uint32_t* b) {
    asm volatile(
        "mma.sync.aligned.m16n8k16.row.col.f32.f16.f16.f32 "
        "{%0,%1,%2,%3},{%4,%5,%6,%7},{%8,%9},{%0,%1,%2,%3};"
        : "+f"(c[0]), "+f"(c[1]), "+f"(c[2]), "+f"(c[3])
        : "r"(a[0]), "r"(a[1]), "r"(a[2]), "r"(a[3]),
          "r"(b[0]), "r"(b[1]));
}
__device__ __forceinline__ void ldsm_x4(uint32_t& r0, uint32_t& r1, uint32_t& r2,
                                        uint32_t& r3, uint32_t addr) {
    asm volatile("ldmatrix.sync.aligned.m8n8.x4.shared.b16 {%0,%1,%2,%3}, [%4];"
                 : "=r"(r0), "=r"(r1), "=r"(r2), "=r"(r3) : "r"(addr));
}
__device__ __forceinline__ void ldsm_x4t(uint32_t& r0, uint32_t& r1, uint32_t& r2,
                                         uint32_t& r3, uint32_t addr) {
    asm volatile("ldmatrix.sync.aligned.m8n8.x4.trans.shared.b16 {%0,%1,%2,%3}, [%4];"
                 : "=r"(r0), "=r"(r1), "=r"(r2), "=r"(r3) : "r"(addr));
}

// ------------------------ fused fp16 GEMM body ------------------------
// A:[M,1024] half row-major; Bt:[N,1024] half row-major (W^T)
// BM=128 x BN=128 CTA tile; 8 warps in 2x4, each 64x32. Double-buffered; 2 CTAs/SM.
// mode 0: bias+phi -> half head-major; 1: bias -> half head-major; 2: bias -> fp32 row-major
__device__ __forceinline__ void gemm_body(
    const __half* __restrict__ A, const __half* __restrict__ Bt,
    const float* __restrict__ bias, float* __restrict__ dstf,
    __half* __restrict__ dsth, int m0, int n0, int mode)
{
    extern __shared__ char smc[];
    const uint32_t smb = s2u(smc);
    const int tid  = threadIdx.x;
    const int wid  = tid >> 5, lane = tid & 31;
    const int wm   = wid >> 2, wn   = wid & 3;   // 2 x 4 warp grid
    const int g    = lane >> 2, tig = lane & 3;

    float acc[4][4][4];
    #pragma unroll
    for (int mt = 0; mt < 4; mt++)
        #pragma unroll
        for (int nt = 0; nt < 4; nt++)
            #pragma unroll
            for (int q = 0; q < 4; q++) acc[mt][nt][q] = 0.f;

    const uint32_t aOff = (uint32_t)((lane & 15) * ROWB + (lane >> 4) * 16);
    const uint32_t bOff = (uint32_t)(((lane & 7) + ((lane >> 4) << 3)) * ROWB
                                     + ((lane >> 3) & 1) * 16);

    auto issue_load = [&](int s, int k0) {
        const uint32_t sb = smb + (uint32_t)s * STAGE_BYTES;
        #pragma unroll
        for (int i = 0; i < 4; i++) {                 // A rows 0..127
            int idx = tid + i * 256, row = idx >> 3, seg = idx & 7;
            const __half* src = A + (size_t)(m0 + row) * DM + k0 + seg * 8;
            asm volatile("cp.async.cg.shared.global [%0], [%1], 16;"
                         :: "r"(sb + (uint32_t)(row * ROWB + seg * 16)), "l"(src));
        }
        #pragma unroll
        for (int i = 4; i < 8; i++) {                 // B rows 128..255
            int idx = tid + i * 256, row = idx >> 3, seg = idx & 7;
            const __half* src = Bt + (size_t)(n0 + row - 128) * DM + k0 + seg * 8;
            asm volatile("cp.async.cg.shared.global [%0], [%1], 16;"
                         :: "r"(sb + (uint32_t)(row * ROWB + seg * 16)), "l"(src));
        }
        asm volatile("cp.async.commit_group;");
    };

    issue_load(0, 0);

    #pragma unroll 1
    for (int kc = 0; kc < NCH; kc++) {
        const int buf = kc & 1;
        if (kc + 1 < NCH) {
            issue_load(buf ^ 1, (kc + 1) * BK);
            asm volatile("cp.async.wait_group 1;");
        } else {
            asm volatile("cp.async.wait_group 0;");
        }
        __syncthreads();

        const uint32_t sb    = smb + (uint32_t)buf * STAGE_BYTES;
        const uint32_t aWarp = sb + (uint32_t)(wm * 64) * ROWB + aOff;
        const uint32_t bWarp = sb + (uint32_t)(128 + wn * 32) * ROWB + bOff;

        #pragma unroll
        for (int kk = 0; kk < 4; kk++) {
            uint32_t a[4][4], b[4][2];
            #pragma unroll
            for (int mt = 0; mt < 4; mt++)
                ldsm_x4(a[mt][0], a[mt][1], a[mt][2], a[mt][3],
                        aWarp + (uint32_t)(mt * 16 * ROWB + kk * 32));
            ldsm_x4(b[0][0], b[0][1], b[1][0], b[1][1], bWarp + (uint32_t)(kk * 32));
            ldsm_x4(b[2][0], b[2][1], b[3][0], b[3][1],
                    bWarp + (uint32_t)(16 * ROWB + kk * 32));
            #pragma unroll
            for (int mt = 0; mt < 4; mt++)
                #pragma unroll
                for (int nt = 0; nt < 4; nt++)
                    mma_f16(acc[mt][nt], a[mt], b[nt]);
        }
        __syncthreads();
    }

    const int mbase = m0 + wm * 64;
    const int nb    = n0 + wn * 32;
    #pragma unroll
    for (int mt = 0; mt < 4; mt++) {
        #pragma unroll
        for (int half = 0; half < 2; half++) {
            const int m = mbase + mt * 16 + g + half * 8;
            #pragma unroll
            for (int nt = 0; nt < 4; nt++) {
                const int c = nb + nt * 8 + 2 * tig;
                float v0 = acc[mt][nt][half * 2 + 0] + bias[c];
                float v1 = acc[mt][nt][half * 2 + 1] + bias[c + 1];
                if (mode == 0) {
                    v0 = (v0 > 0.f) ? (v0 + 1.f) : __expf(v0);
                    v1 = (v1 > 0.f) ? (v1 + 1.f) : __expf(v1);
                }
                if (mode == 2) {
                    *(float2*)&dstf[(size_t)m * DM + c] = make_float2(v0, v1);
                } else {
                    const int b2 = m >> 9, n = m & 511;
                    const int h = c >> 6, d = c & 63;
                    *(__half2*)&dsth[((((size_t)(b2 * NH + h)) * SEQ + n) << 6) + d] =
                        __floats2half2_rn(v0, v1);
                }
            }
        }
    }
}

// ------------------------ kernels ------------------------
__global__ __launch_bounds__(256, 2) void qkv_mma(
    const float* __restrict__ bq, const float* __restrict__ bk, const float* __restrict__ bv)
{
    const int z = blockIdx.z;
    const float* bias = (z == 0) ? bq : (z == 1) ? bk : bv;
    __half* dst       = (z == 0) ? g_qfh : (z == 1) ? g_kfh : g_vh;
    gemm_body(g_xh, g_wth[z], bias, nullptr, dst,
              blockIdx.y * BM, blockIdx.x * BN, (z < 2) ? 0 : 1);
}

__global__ __launch_bounds__(256, 2) void out_mma(
    const float* __restrict__ bo, float* __restrict__ out)
{
    gemm_body(g_ath, g_wth[3], bo, out, nullptr, blockIdx.y * BM, blockIdx.x * BN, 2);
}

__global__ __launch_bounds__(256) void cvt_x_kernel(const float* __restrict__ x)
{
    int idx = blockIdx.x * 256 + threadIdx.x;
    float4 v = ((const float4*)x)[idx];
    ((__half2*)g_xh)[idx * 2 + 0] = __floats2half2_rn(v.x, v.y);
    ((__half2*)g_xh)[idx * 2 + 1] = __floats2half2_rn(v.z, v.w);
}

__global__ __launch_bounds__(256) void transpose_w(
    const float* __restrict__ Wq, const float* __restrict__ Wk,
    const float* __restrict__ Wv, const float* __restrict__ Wo)
{
    const int z = blockIdx.z;
    const float* W = (z == 0) ? Wq : (z == 1) ? Wk : (z == 2) ? Wv : Wo;
    __half* dst = g_wth[z];
    __shared__ float t[32][33];
    const int k0 = blockIdx.x * 32, n0 = blockIdx.y * 32;
    const int tx = threadIdx.x & 31, ty = threadIdx.x >> 5;
    #pragma unroll
    for (int i = 0; i < 4; i++)
        t[ty + i*8][tx] = W[(size_t)(k0 + ty + i*8) * DM + n0 + tx];
    __syncthreads();
    #pragma unroll
    for (int i = 0; i < 4; i++)
        dst[(size_t)(n0 + ty + i*8) * DM + k0 + tx] = __float2half_rn(t[tx][ty + i*8]);
}

// K2: kv^T[e][d] = sum_n kf[n][d]*v[n][e] via HMMA (trans ldmatrix); fused ksum. (R10)
#define KVROW 72   // padded row stride in halves (144B)
__global__ __launch_bounds__(128) void kv_kernel()
{
    const int bh = blockIdx.x;
    const __half* kf = g_kfh + (size_t)bh * SEQ * DK;
    const __half* v  = g_vh  + (size_t)bh * SEQ * DK;

    __shared__ __half kfs[2][64 * KVROW];
    __shared__ __half vs [2][64 * KVROW];

    const int tid  = threadIdx.x;
    const int wid  = tid >> 5, lane = tid & 31;
    const int wm   = wid >> 1, wn = wid & 1;       // 2x2 warp grid
    const int d_base = wm * 32, e_base = wn * 32;
    const int g8   = lane >> 3, r8 = lane & 7;
    const int g    = lane >> 2, tig = lane & 3;

    const uint32_t aTO = (uint32_t)((((g8 >> 1) * 8) + r8) * 2 * KVROW + ((g8 & 1) * 8) * 2);
    const uint32_t bTO = (uint32_t)((((g8 & 1) * 8) + r8) * 2 * KVROW + ((g8 >> 1) * 8) * 2);

    auto issue = [&](int s, int c) {
        uint32_t dk = s2u(&kfs[s][0]);
        uint32_t dv = s2u(&vs [s][0]);
        #pragma unroll
        for (int i = 0; i < 4; i++) {
            int idx = tid + i * 128, row = idx >> 3, seg = idx & 7;
            uint32_t off = (uint32_t)(row * (KVROW * 2) + seg * 16);
            const __half* sk = kf + (size_t)(c + row) * 64 + seg * 8;
            const __half* sv = v  + (size_t)(c + row) * 64 + seg * 8;
            asm volatile("cp.async.cg.shared.global [%0], [%1], 16;" :: "r"(dk + off), "l"(sk));
            asm volatile("cp.async.cg.shared.global [%0], [%1], 16;" :: "r"(dv + off), "l"(sv));
        }
        asm volatile("cp.async.commit_group;");
    };

    float acc[2][4][4];
    #pragma unroll
    for (int mt = 0; mt < 2; mt++)
        #pragma unroll
        for (int nt = 0; nt < 4; nt++)
            #pragma unroll
            for (int q = 0; q < 4; q++) acc[mt][nt][q] = 0.f;
    float ks = 0.f;

    issue(0, 0);
    for (int cc = 0; cc < SEQ / 64; cc++) {
        const int buf = cc & 1;
        if (cc + 1 < SEQ / 64) {
            issue(buf ^ 1, (cc + 1) * 64);
            asm volatile("cp.async.wait_group 1;");
        } else {
            asm volatile("cp.async.wait_group 0;");
        }
        __syncthreads();

        const uint32_t kb = s2u(&kfs[buf][0]);
        const uint32_t vb = s2u(&vs [buf][0]);

        #pragma unroll
        for (int kk = 0; kk < 4; kk++) {
            const uint32_t nb0 = (uint32_t)(kk * 16) * (KVROW * 2);
            uint32_t a[2][4], b[4][2];
            #pragma unroll
            for (int mt = 0; mt < 2; mt++)
                ldsm_x4t(a[mt][0], a[mt][1], a[mt][2], a[mt][3],
                         kb + nb0 + (uint32_t)(d_base + mt * 16) * 2 + aTO);
            #pragma unroll
            for (int p = 0; p < 2; p++) {
                uint32_t addr = vb + nb0 + (uint32_t)(e_base + p * 16) * 2 + bTO;
                ldsm_x4t(b[p*2][0], b[p*2][1], b[p*2+1][0], b[p*2+1][1], addr);
            }
            #pragma unroll
            for (int mt = 0; mt < 2; mt++)
                #pragma unroll
                for (int nt = 0; nt < 4; nt++)
                    mma_f16(acc[mt][nt], a[mt], b[nt]);
        }

        if (tid < 64) {
            #pragma unroll 8
            for (int n = 0; n < 64; n++)
                ks += __half2float(kfs[buf][n * KVROW + tid]);
        }
        __syncthreads();
    }

    __half* kvt = g_kvT + (size_t)bh * DK * DK;
    #pragma unroll
    for (int mt = 0; mt < 2; mt++) {
        #pragma unroll
        for (int half = 0; half < 2; half++) {
            const int d = d_base + mt * 16 + g + half * 8;
            #pragma unroll
            for (int nt = 0; nt < 4; nt++) {
                const int e = e_base + nt * 8 + 2 * tig;
                kvt[(size_t)e * DK + d]       = __float2half_rn(acc[mt][nt][half*2+0]);
                kvt[(size_t)(e+1) * DK + d]   = __float2half_rn(acc[mt][nt][half*2+1]);
            }
        }
    }
    if (tid < 64) g_ks[(size_t)bh * DK + tid] = ks;
}

// K3: out = qf @ kv / den via HMMA. 256 threads (8 warps), grid 512. (R10)
#define AT_QBYTES (SEQ * KVROW * 2)        // 73728
#define AT_KVOFF  AT_QBYTES
#define AT_KSOFF  (AT_KVOFF + 64 * KVROW * 2)   // 82944
#define AT_DENOFF (AT_KSOFF + 64 * 4)           // 83200
#define AT_SMEM   (AT_DENOFF + SEQ * 4)         // 85248
__global__ __launch_bounds__(256) void attn_kernel()
{
    const int bh = blockIdx.x;
    const int b = bh >> 4, h = bh & 15;

    extern __shared__ char smc[];
    __half* qfs = (__half*)smc;
    float*  kss = (float*)(smc + AT_KSOFF);
    float*  den = (float*)(smc + AT_DENOFF);
    const uint32_t smb = s2u(smc);

    const int tid  = threadIdx.x;
    const int wid  = tid >> 5, lane = tid & 31;
    const int g    = lane >> 2, tig = lane & 3;

    const __half* qf  = g_qfh + (size_t)bh * SEQ * DK;
    const __half* kvt = g_kvT + (size_t)bh * DK * DK;

    {
        uint32_t dq = smb;
        #pragma unroll
        for (int i = 0; i < 16; i++) {
            int idx = tid + i * 256, row = idx >> 3, seg = idx & 7;
            const __half* src = qf + (size_t)row * 64 + seg * 8;
            asm volatile("cp.async.cg.shared.global [%0], [%1], 16;"
                         :: "r"(dq + (uint32_t)(row * (KVROW*2) + seg * 16)), "l"(src));
        }
        uint32_t dk = smb + AT_KVOFF;
        #pragma unroll
        for (int i = 0; i < 2; i++) {
            int idx = tid + i * 256, row = idx >> 3, seg = idx & 7;
            const __half* src = kvt + (size_t)row * 64 + seg * 8;
            asm volatile("cp.async.cg.shared.global [%0], [%1], 16;"
                         :: "r"(dk + (uint32_t)(row * (KVROW*2) + seg * 16)), "l"(src));
        }
        asm volatile("cp.async.commit_group;");
    }
    if (tid < 64) kss[tid] = g_ks[(size_t)bh * DK + tid];
    asm volatile("cp.async.wait_group 0;");
    __syncthreads();

    #pragma unroll
    for (int rr = 0; rr < 2; rr++) {
        const int n = tid + rr * 256;
        const __half* qr = qfs + (size_t)n * KVROW;
        float dsum = 0.f;
        #pragma unroll 16
        for (int d = 0; d < 64; d++) dsum += __half2float(qr[d]) * kss[d];
        den[n] = 1.f / (dsum + EPSV);
    }
    __syncthreads();

    const uint32_t aOff = (uint32_t)((lane & 15) * (KVROW*2) + (lane >> 4) * 16);
    const uint32_t bOff = (uint32_t)(((lane & 7) + ((lane >> 4) << 3)) * (KVROW*2)
                                     + ((lane >> 3) & 1) * 16);
    const int m_base = wid * 64;
    const uint32_t aWarp = smb + (uint32_t)m_base * (KVROW*2) + aOff;
    const uint32_t bWarp = smb + AT_KVOFF + bOff;

    __half* outp = g_ath;
    #pragma unroll
    for (int nh = 0; nh < 2; nh++) {
        float acc[4][4][4];
        #pragma unroll
        for (int mt = 0; mt < 4; mt++)
            #pragma unroll
            for (int nt = 0; nt < 4; nt++)
                #pragma unroll
                for (int q = 0; q < 4; q++) acc[mt][nt][q] = 0.f;

        #pragma unroll
        for (int kk = 0; kk < 4; kk++) {
            uint32_t a[4][4], b[4][2];
            #pragma unroll
            for (int mt = 0; mt < 4; mt++)
                ldsm_x4(a[mt][0], a[mt][1], a[mt][2], a[mt][3],
                        aWarp + (uint32_t)(mt * 16 * (KVROW*2) + kk * 32));
            ldsm_x4(b[0][0], b[0][1], b[1][0], b[1][1],
                    bWarp + (uint32_t)((nh * 32) * (KVROW*2) + kk * 32));
            ldsm_x4(b[2][0], b[2][1], b[3][0], b[3][1],
                    bWarp + (uint32_t)((nh * 32 + 16) * (KVROW*2) + kk * 32));
            #pragma unroll
            for (int mt = 0; mt < 4; mt++)
                #pragma unroll
                for (int nt = 0; nt < 4; nt++)
                    mma_f16(acc[mt][nt], a[mt], b[nt]);
        }

        #pragma unroll
        for (int mt = 0; mt < 4; mt++) {
            #pragma unroll
            for (int half = 0; half < 2; half++) {
                const int m = m_base + mt * 16 + g + half * 8;
                const float inv = den[m];
                const size_t o = (((size_t)(b * SEQ + m)) * NH + h) * 64;
                #pragma unroll
                for (int nt = 0; nt < 4; nt++) {
                    const int e = nh * 32 + nt * 8 + 2 * tig;
                    *(__half2*)&outp[o + e] = __floats2half2_rn(
                        acc[mt][nt][half*2+0] * inv, acc[mt][nt][half*2+1] * inv);
                }
            }
        }
    }
}

// ---------------------------------------------------------------
extern "C" void kernel_launch(void* const* d_in, const int* in_sizes, int n_in,
                              void* d_out, int out_size)
{
    const float* x  = (const float*)d_in[0];
    const float* Wq = (const float*)d_in[1];
    const float* bq = (const float*)d_in[2];
    const float* Wk = (const float*)d_in[3];
    const float* bk = (const float*)d_in[4];
    const float* Wv = (const float*)d_in[5];
    const float* bv = (const float*)d_in[6];
    const float* Wo = (const float*)d_in[7];
    const float* bo = (const float*)d_in[8];
    float* out = (float*)d_out;

    cudaFuncSetAttribute(qkv_mma, cudaFuncAttributeMaxDynamicSharedMemorySize, SMEM_BYTES);
    cudaFuncSetAttribute(out_mma, cudaFuncAttributeMaxDynamicSharedMemorySize, SMEM_BYTES);
    cudaFuncSetAttribute(attn_kernel, cudaFuncAttributeMaxDynamicSharedMemorySize, AT_SMEM);

    cvt_x_kernel<<<(MTOK * DM / 4) / 256, 256>>>(x);
    transpose_w<<<dim3(DM/32, DM/32, 4), 256>>>(Wq, Wk, Wv, Wo);

    dim3 gq(DM / BN, MTOK / BM, 3);          // (8, 128, 3)
    qkv_mma<<<gq, 256, SMEM_BYTES>>>(bq, bk, bv);

    kv_kernel<<<BATCH * NH, 128>>>();
    attn_kernel<<<BATCH * NH, 256, AT_SMEM>>>();

    dim3 go(DM / BN, MTOK / BM);             // (8, 128)
    out_mma<<<go, 256, SMEM_BYTES>>>(bo, out);
}

// round 17
// speedup vs baseline: 1.0985x; 1.0068x over previous
#include <cuda_runtime.h>
#include <cuda_fp16.h>
#include <stdint.h>

#define DM    1024
#define NH    16
#define DK    64
#define BATCH 32
#define SEQ   512
#define MTOK  (BATCH*SEQ)   // 16384
#define EPSV  1e-6f

#define BM 128
#define BN 128
#define BK 64                        // halves per K chunk (128B row)
#define NCH (DM/BK)                  // 16
#define ROWB 144                     // padded row stride in bytes (128 + 16)
#define STAGE_BYTES ((BM+BN)*ROWB)   // 36864
#define SMEM_BYTES (2*STAGE_BYTES)   // 73728  (2 stages -> 2 CTAs/SM)

// -------- scratch (static __device__, no runtime allocation) --------
__device__ __half g_xh[(size_t)MTOK * DM];       // half(x)
__device__ __half g_wth[4][(size_t)DM * DM];     // transposed half W{q,k,v,o}: [N,K]
__device__ __half g_qfh[(size_t)MTOK * DM];      // phi(Q) half, head-major [B,H,N,Dk]
__device__ __half g_kfh[(size_t)MTOK * DM];      // phi(K) half, head-major
__device__ __half g_vh [(size_t)MTOK * DM];      // V half, head-major
__device__ __half g_ath[(size_t)MTOK * DM];      // attn out half, token-major [B,N,H,Dk]
__device__ __half g_kvT[(size_t)BATCH * NH * DK * DK];  // kv^T [e][d], half
__device__ float  g_ks[(size_t)BATCH * NH * DK];

// ------------------------ helpers ------------------------
__device__ __forceinline__ uint32_t s2u(const void* p) {
    return (uint32_t)__cvta_generic_to_shared(p);
}
__device__ __forceinline__ void mma_f16(float* c, const uint32_t* a, const uint32_t* b) {
    asm volatile(
        "mma.sync.aligned.m16n8k16.row.col.f32.f16.f16.f32 "
        "{%0,%1,%2,%3},{%4,%5,%6,%7},{%8,%9},{%0,%1,%2,%3};"
        : "+f"(c[0]), "+f"(c[1]), "+f"(c[2]), "+f"(c[3])
        : "r"(a[0]), "r"(a[1]), "r"(a[2]), "r"(a[3]),
          "r"(b[0]), "r"(b[1]));
}
__device__ __forceinline__ void ldsm_x4(uint32_t& r0, uint32_t& r1, uint32_t& r2,
                                        uint32_t& r3, uint32_t addr) {
    asm volatile("ldmatrix.sync.aligned.m8n8.x4.shared.b16 {%0,%1,%2,%3}, [%4];"
                 : "=r"(r0), "=r"(r1), "=r"(r2), "=r"(r3) : "r"(addr));
}
__device__ __forceinline__ void ldsm_x4t(uint32_t& r0, uint32_t& r1, uint32_t& r2,
                                         uint32_t& r3, uint32_t addr) {
    asm volatile("ldmatrix.sync.aligned.m8n8.x4.trans.shared.b16 {%0,%1,%2,%3}, [%4];"
                 : "=r"(r0), "=r"(r1), "=r"(r2), "=r"(r3) : "r"(addr));
}

// ------------------------ fused fp16 GEMM body (R15 form — unchanged) ------------------------
__device__ __forceinline__ void gemm_body(
    const __half* __restrict__ A, const __half* __restrict__ Bt,
    const float* __restrict__ bias, float* __restrict__ dstf,
    __half* __restrict__ dsth, int m0, int n0, int mode)
{
    extern __shared__ char smc[];
    const uint32_t smb = s2u(smc);
    const int tid  = threadIdx.x;
    const int wid  = tid >> 5, lane = tid & 31;
    const int wm   = wid >> 2, wn   = wid & 3;   // 2 x 4 warp grid
    const int g    = lane >> 2, tig = lane & 3;

    float acc[4][4][4];
    #pragma unroll
    for (int mt = 0; mt < 4; mt++)
        #pragma unroll
        for (int nt = 0; nt < 4; nt++)
            #pragma unroll
            for (int q = 0; q < 4; q++) acc[mt][nt][q] = 0.f;

    const uint32_t aOff = (uint32_t)((lane & 15) * ROWB + (lane >> 4) * 16);
    const uint32_t bOff = (uint32_t)(((lane & 7) + ((lane >> 4) << 3)) * ROWB
                                     + ((lane >> 3) & 1) * 16);

    auto issue_load = [&](int s, int k0) {
        const uint32_t sb = smb + (uint32_t)s * STAGE_BYTES;
        #pragma unroll
        for (int i = 0; i < 4; i++) {                 // A rows 0..127
            int idx = tid + i * 256, row = idx >> 3, seg = idx & 7;
            const __half* src = A + (size_t)(m0 + row) * DM + k0 + seg * 8;
            asm volatile("cp.async.cg.shared.global [%0], [%1], 16;"
                         :: "r"(sb + (uint32_t)(row * ROWB + seg * 16)), "l"(src));
        }
        #pragma unroll
        for (int i = 4; i < 8; i++) {                 // B rows 128..255
            int idx = tid + i * 256, row = idx >> 3, seg = idx & 7;
            const __half* src = Bt + (size_t)(n0 + row - 128) * DM + k0 + seg * 8;
            asm volatile("cp.async.cg.shared.global [%0], [%1], 16;"
                         :: "r"(sb + (uint32_t)(row * ROWB + seg * 16)), "l"(src));
        }
        asm volatile("cp.async.commit_group;");
    };

    issue_load(0, 0);

    #pragma unroll 1
    for (int kc = 0; kc < NCH; kc++) {
        const int buf = kc & 1;
        if (kc + 1 < NCH) {
            issue_load(buf ^ 1, (kc + 1) * BK);
            asm volatile("cp.async.wait_group 1;");
        } else {
            asm volatile("cp.async.wait_group 0;");
        }
        __syncthreads();

        const uint32_t sb    = smb + (uint32_t)buf * STAGE_BYTES;
        const uint32_t aWarp = sb + (uint32_t)(wm * 64) * ROWB + aOff;
        const uint32_t bWarp = sb + (uint32_t)(128 + wn * 32) * ROWB + bOff;

        #pragma unroll
        for (int kk = 0; kk < 4; kk++) {
            uint32_t a[4][4], b[4][2];
            #pragma unroll
            for (int mt = 0; mt < 4; mt++)
                ldsm_x4(a[mt][0], a[mt][1], a[mt][2], a[mt][3],
                        aWarp + (uint32_t)(mt * 16 * ROWB + kk * 32));
            ldsm_x4(b[0][0], b[0][1], b[1][0], b[1][1], bWarp + (uint32_t)(kk * 32));
            ldsm_x4(b[2][0], b[2][1], b[3][0], b[3][1],
                    bWarp + (uint32_t)(16 * ROWB + kk * 32));
            #pragma unroll
            for (int mt = 0; mt < 4; mt++)
                #pragma unroll
                for (int nt = 0; nt < 4; nt++)
                    mma_f16(acc[mt][nt], a[mt], b[nt]);
        }
        __syncthreads();
    }

    const int mbase = m0 + wm * 64;
    const int nb    = n0 + wn * 32;
    #pragma unroll
    for (int mt = 0; mt < 4; mt++) {
        #pragma unroll
        for (int half = 0; half < 2; half++) {
            const int m = mbase + mt * 16 + g + half * 8;
            #pragma unroll
            for (int nt = 0; nt < 4; nt++) {
                const int c = nb + nt * 8 + 2 * tig;
                float v0 = acc[mt][nt][half * 2 + 0] + bias[c];
                float v1 = acc[mt][nt][half * 2 + 1] + bias[c + 1];
                if (mode == 0) {
                    v0 = (v0 > 0.f) ? (v0 + 1.f) : __expf(v0);
                    v1 = (v1 > 0.f) ? (v1 + 1.f) : __expf(v1);
                }
                if (mode == 2) {
                    *(float2*)&dstf[(size_t)m * DM + c] = make_float2(v0, v1);
                } else {
                    const int b2 = m >> 9, n = m & 511;
                    const int h = c >> 6, d = c & 63;
                    *(__half2*)&dsth[((((size_t)(b2 * NH + h)) * SEQ + n) << 6) + d] =
                        __floats2half2_rn(v0, v1);
                }
            }
        }
    }
}

// ------------------------ kernels ------------------------
__global__ __launch_bounds__(256, 2) void qkv_mma(
    const float* __restrict__ bq, const float* __restrict__ bk, const float* __restrict__ bv)
{
    const int z = blockIdx.z;
    const float* bias = (z == 0) ? bq : (z == 1) ? bk : bv;
    __half* dst       = (z == 0) ? g_qfh : (z == 1) ? g_kfh : g_vh;
    gemm_body(g_xh, g_wth[z], bias, nullptr, dst,
              blockIdx.y * BM, blockIdx.x * BN, (z < 2) ? 0 : 1);
}

__global__ __launch_bounds__(256, 2) void out_mma(
    const float* __restrict__ bo, float* __restrict__ out)
{
    gemm_body(g_ath, g_wth[3], bo, out, nullptr, blockIdx.y * BM, blockIdx.x * BN, 2);
}

// merged prep: bid < 16384 -> convert x slice; else -> transpose a 32x32 W tile
#define CVT_BLOCKS (MTOK * DM / 4 / 256)       // 16384
__global__ __launch_bounds__(256) void prep_kernel(
    const float* __restrict__ x,
    const float* __restrict__ Wq, const float* __restrict__ Wk,
    const float* __restrict__ Wv, const float* __restrict__ Wo)
{
    const int bid = blockIdx.x;
    if (bid < CVT_BLOCKS) {
        int idx = bid * 256 + threadIdx.x;
        float4 v = ((const float4*)x)[idx];
        ((__half2*)g_xh)[idx * 2 + 0] = __floats2half2_rn(v.x, v.y);
        ((__half2*)g_xh)[idx * 2 + 1] = __floats2half2_rn(v.z, v.w);
        return;
    }
    const int t = bid - CVT_BLOCKS;            // 0 .. 4*32*32-1
    const int z  = t >> 10;                    // /1024
    const int r  = t & 1023;
    const int kb = r & 31, nb = r >> 5;
    const float* W = (z == 0) ? Wq : (z == 1) ? Wk : (z == 2) ? Wv : Wo;
    __half* dst = g_wth[z];
    __shared__ float tt[32][33];
    const int k0 = kb * 32, n0 = nb * 32;
    const int tx = threadIdx.x & 31, ty = threadIdx.x >> 5;
    #pragma unroll
    for (int i = 0; i < 4; i++)
        tt[ty + i*8][tx] = W[(size_t)(k0 + ty + i*8) * DM + n0 + tx];
    __syncthreads();
    #pragma unroll
    for (int i = 0; i < 4; i++)
        dst[(size_t)(n0 + ty + i*8) * DM + k0 + tx] = __float2half_rn(tt[tx][ty + i*8]);
}

// K2: kv^T[e][d] = sum_n kf[n][d]*v[n][e] via HMMA; 256 threads (2x4 warp grid, 32x16 tiles)
#define KVROW 72   // padded row stride in halves (144B)
__global__ __launch_bounds__(256) void kv_kernel()
{
    const int bh = blockIdx.x;
    const __half* kf = g_kfh + (size_t)bh * SEQ * DK;
    const __half* v  = g_vh  + (size_t)bh * SEQ * DK;

    __shared__ __half kfs[2][64 * KVROW];
    __shared__ __half vs [2][64 * KVROW];

    const int tid  = threadIdx.x;
    const int wid  = tid >> 5, lane = tid & 31;
    const int wm   = wid >> 2, wn = wid & 3;       // 2x4 warp grid
    const int d_base = wm * 32, e_base = wn * 16;
    const int g8   = lane >> 3, r8 = lane & 7;
    const int g    = lane >> 2, tig = lane & 3;

    const uint32_t aTO = (uint32_t)((((g8 >> 1) * 8) + r8) * 2 * KVROW + ((g8 & 1) * 8) * 2);
    const uint32_t bTO = (uint32_t)((((g8 & 1) * 8) + r8) * 2 * KVROW + ((g8 >> 1) * 8) * 2);

    auto issue = [&](int s, int c) {
        uint32_t dk = s2u(&kfs[s][0]);
        uint32_t dv = s2u(&vs [s][0]);
        #pragma unroll
        for (int i = 0; i < 2; i++) {
            int idx = tid + i * 256, row = idx >> 3, seg = idx & 7;
            uint32_t off = (uint32_t)(row * (KVROW * 2) + seg * 16);
            const __half* sk = kf + (size_t)(c + row) * 64 + seg * 8;
            const __half* sv = v  + (size_t)(c + row) * 64 + seg * 8;
            asm volatile("cp.async.cg.shared.global [%0], [%1], 16;" :: "r"(dk + off), "l"(sk));
            asm volatile("cp.async.cg.shared.global [%0], [%1], 16;" :: "r"(dv + off), "l"(sv));
        }
        asm volatile("cp.async.commit_group;");
    };

    float acc[2][2][4];
    #pragma unroll
    for (int mt = 0; mt < 2; mt++)
        #pragma unroll
        for (int nt = 0; nt < 2; nt++)
            #pragma unroll
            for (int q = 0; q < 4; q++) acc[mt][nt][q] = 0.f;
    float ks = 0.f;

    issue(0, 0);
    for (int cc = 0; cc < SEQ / 64; cc++) {
        const int buf = cc & 1;
        if (cc + 1 < SEQ / 64) {
            issue(buf ^ 1, (cc + 1) * 64);
            asm volatile("cp.async.wait_group 1;");
        } else {
            asm volatile("cp.async.wait_group 0;");
        }
        __syncthreads();

        const uint32_t kb = s2u(&kfs[buf][0]);
        const uint32_t vb = s2u(&vs [buf][0]);

        #pragma unroll
        for (int kk = 0; kk < 4; kk++) {
            const uint32_t nb0 = (uint32_t)(kk * 16) * (KVROW * 2);
            uint32_t a[2][4], bfr[2][2];
            #pragma unroll
            for (int mt = 0; mt < 2; mt++)
                ldsm_x4t(a[mt][0], a[mt][1], a[mt][2], a[mt][3],
                         kb + nb0 + (uint32_t)(d_base + mt * 16) * 2 + aTO);
            ldsm_x4t(bfr[0][0], bfr[0][1], bfr[1][0], bfr[1][1],
                     vb + nb0 + (uint32_t)e_base * 2 + bTO);
            #pragma unroll
            for (int mt = 0; mt < 2; mt++)
                #pragma unroll
                for (int nt = 0; nt < 2; nt++)
                    mma_f16(acc[mt][nt], a[mt], bfr[nt]);
        }

        if (tid < 64) {
            #pragma unroll 8
            for (int n = 0; n < 64; n++)
                ks += __half2float(kfs[buf][n * KVROW + tid]);
        }
        __syncthreads();
    }

    __half* kvt = g_kvT + (size_t)bh * DK * DK;
    #pragma unroll
    for (int mt = 0; mt < 2; mt++) {
        #pragma unroll
        for (int half = 0; half < 2; half++) {
            const int d = d_base + mt * 16 + g + half * 8;
            #pragma unroll
            for (int nt = 0; nt < 2; nt++) {
                const int e = e_base + nt * 8 + 2 * tig;
                kvt[(size_t)e * DK + d]       = __float2half_rn(acc[mt][nt][half*2+0]);
                kvt[(size_t)(e+1) * DK + d]   = __float2half_rn(acc[mt][nt][half*2+1]);
            }
        }
    }
    if (tid < 64) g_ks[(size_t)bh * DK + tid] = ks;
}

// K3: out = qf @ kv / den via HMMA. Split qf prefetch to overlap den compute with load.
#define AT_QBYTES (SEQ * KVROW * 2)        // 73728
#define AT_HALFQ  (256 * KVROW * 2)        // 36864
#define AT_KVOFF  AT_QBYTES
#define AT_KSOFF  (AT_KVOFF + 64 * KVROW * 2)   // 82944
#define AT_DENOFF (AT_KSOFF + 64 * 4)           // 83200
#define AT_SMEM   (AT_DENOFF + SEQ * 4)         // 85248
__global__ __launch_bounds__(256) void attn_kernel()
{
    const int bh = blockIdx.x;
    const int b = bh >> 4, h = bh & 15;

    extern __shared__ char smc[];
    __half* qfs = (__half*)smc;
    float*  kss = (float*)(smc + AT_KSOFF);
    float*  den = (float*)(smc + AT_DENOFF);
    const uint32_t smb = s2u(smc);

    const int tid  = threadIdx.x;
    const int wid  = tid >> 5, lane = tid & 31;
    const int g    = lane >> 2, tig = lane & 3;

    const __half* qf  = g_qfh + (size_t)bh * SEQ * DK;
    const __half* kvt = g_kvT + (size_t)bh * DK * DK;

    // group A: qf rows 0..255
    #pragma unroll
    for (int i = 0; i < 8; i++) {
        int idx = tid + i * 256, row = idx >> 3, seg = idx & 7;
        const __half* src = qf + (size_t)row * 64 + seg * 8;
        asm volatile("cp.async.cg.shared.global [%0], [%1], 16;"
                     :: "r"(smb + (uint32_t)(row * (KVROW*2) + seg * 16)), "l"(src));
    }
    asm volatile("cp.async.commit_group;");
    // group B: qf rows 256..511 + kvT
    #pragma unroll
    for (int i = 8; i < 16; i++) {
        int idx = tid + i * 256, row = idx >> 3, seg = idx & 7;
        const __half* src = qf + (size_t)row * 64 + seg * 8;
        asm volatile("cp.async.cg.shared.global [%0], [%1], 16;"
                     :: "r"(smb + (uint32_t)(row * (KVROW*2) + seg * 16)), "l"(src));
    }
    {
        uint32_t dk = smb + AT_KVOFF;
        #pragma unroll
        for (int i = 0; i < 2; i++) {
            int idx = tid + i * 256, row = idx >> 3, seg = idx & 7;
            const __half* src = kvt + (size_t)row * 64 + seg * 8;
            asm volatile("cp.async.cg.shared.global [%0], [%1], 16;"
                         :: "r"(dk + (uint32_t)(row * (KVROW*2) + seg * 16)), "l"(src));
        }
    }
    asm volatile("cp.async.commit_group;");

    if (tid < 64) kss[tid] = g_ks[(size_t)bh * DK + tid];

    // first half denominators overlap group-B load
    asm volatile("cp.async.wait_group 1;");
    __syncthreads();
    {
        const __half* qr = qfs + (size_t)tid * KVROW;
        float dsum = 0.f;
        #pragma unroll 16
        for (int d = 0; d < 64; d++) dsum += __half2float(qr[d]) * kss[d];
        den[tid] = 1.f / (dsum + EPSV);
    }
    asm volatile("cp.async.wait_group 0;");
    __syncthreads();
    {
        const int n = tid + 256;
        const __half* qr = qfs + (size_t)n * KVROW;
        float dsum = 0.f;
        #pragma unroll 16
        for (int d = 0; d < 64; d++) dsum += __half2float(qr[d]) * kss[d];
        den[n] = 1.f / (dsum + EPSV);
    }
    __syncthreads();

    const uint32_t aOff = (uint32_t)((lane & 15) * (KVROW*2) + (lane >> 4) * 16);
    const uint32_t bOff = (uint32_t)(((lane & 7) + ((lane >> 4) << 3)) * (KVROW*2)
                                     + ((lane >> 3) & 1) * 16);
    const int m_base = wid * 64;
    const uint32_t aWarp = smb + (uint32_t)m_base * (KVROW*2) + aOff;
    const uint32_t bWarp = smb + AT_KVOFF + bOff;

    __half* outp = g_ath;
    #pragma unroll
    for (int nh = 0; nh < 2; nh++) {
        float acc[4][4][4];
        #pragma unroll
        for (int mt = 0; mt < 4; mt++)
            #pragma unroll
            for (int nt = 0; nt < 4; nt++)
                #pragma unroll
                for (int q = 0; q < 4; q++) acc[mt][nt][q] = 0.f;

        #pragma unroll
        for (int kk = 0; kk < 4; kk++) {
            uint32_t a[4][4], bfr[4][2];
            #pragma unroll
            for (int mt = 0; mt < 4; mt++)
                ldsm_x4(a[mt][0], a[mt][1], a[mt][2], a[mt][3],
                        aWarp + (uint32_t)(mt * 16 * (KVROW*2) + kk * 32));
            ldsm_x4(bfr[0][0], bfr[0][1], bfr[1][0], bfr[1][1],
                    bWarp + (uint32_t)((nh * 32) * (KVROW*2) + kk * 32));
            ldsm_x4(bfr[2][0], bfr[2][1], bfr[3][0], bfr[3][1],
                    bWarp + (uint32_t)((nh * 32 + 16) * (KVROW*2) + kk * 32));
            #pragma unroll
            for (int mt = 0; mt < 4; mt++)
                #pragma unroll
                for (int nt = 0; nt < 4; nt++)
                    mma_f16(acc[mt][nt], a[mt], bfr[nt]);
        }

        #pragma unroll
        for (int mt = 0; mt < 4; mt++) {
            #pragma unroll
            for (int half = 0; half < 2; half++) {
                const int m = m_base + mt * 16 + g + half * 8;
                const float inv = den[m];
                const size_t o = (((size_t)(b * SEQ + m)) * NH + h) * 64;
                #pragma unroll
                for (int nt = 0; nt < 4; nt++) {
                    const int e = nh * 32 + nt * 8 + 2 * tig;
                    *(__half2*)&outp[o + e] = __floats2half2_rn(
                        acc[mt][nt][half*2+0] * inv, acc[mt][nt][half*2+1] * inv);
                }
            }
        }
    }
}

// ---------------------------------------------------------------
extern "C" void kernel_launch(void* const* d_in, const int* in_sizes, int n_in,
                              void* d_out, int out_size)
{
    const float* x  = (const float*)d_in[0];
    const float* Wq = (const float*)d_in[1];
    const float* bq = (const float*)d_in[2];
    const float* Wk = (const float*)d_in[3];
    const float* bk = (const float*)d_in[4];
    const float* Wv = (const float*)d_in[5];
    const float* bv = (const float*)d_in[6];
    const float* Wo = (const float*)d_in[7];
    const float* bo = (const float*)d_in[8];
    float* out = (float*)d_out;

    cudaFuncSetAttribute(qkv_mma, cudaFuncAttributeMaxDynamicSharedMemorySize, SMEM_BYTES);
    cudaFuncSetAttribute(out_mma, cudaFuncAttributeMaxDynamicSharedMemorySize, SMEM_BYTES);
    cudaFuncSetAttribute(attn_kernel, cudaFuncAttributeMaxDynamicSharedMemorySize, AT_SMEM);

    prep_kernel<<<CVT_BLOCKS + 4 * 32 * 32, 256>>>(x, Wq, Wk, Wv, Wo);

    dim3 gq(DM / BN, MTOK / BM, 3);          // (8, 128, 3)
    qkv_mma<<<gq, 256, SMEM_BYTES>>>(bq, bk, bv);

    kv_kernel<<<BATCH * NH, 256>>>();
    attn_kernel<<<BATCH * NH, 256, AT_SMEM>>>();

    dim3 go(DM / BN, MTOK / BM);             // (8, 128)
    out_mma<<<go, 256, SMEM_BYTES>>>(bo, out);
}